// round 7
// baseline (speedup 1.0000x reference)
#include <cuda_runtime.h>
#include <cuda_bf16.h>

// Depthwise 3x3 conv, pad=1: x (2,16,256,64,64) fp32, W (256,256,3,3) -> diag only.
#define C_CH   256
#define H_SP   64
#define W_SP   64
#define N_IMG  (2 * 16 * C_CH)   // 8192 images of 64x64

__device__ __forceinline__ float4 f4zero() { return make_float4(0.f, 0.f, 0.f, 0.f); }

// Horizontal halo: l = previous lane's .w, r = next lane's .x, zeroed at
// the 16-lane group boundaries (each 16-lane group covers one 64-wide row).
__device__ __forceinline__ void halo(const float4& v, int lane16, float& l, float& r)
{
    l = __shfl_up_sync(0xffffffffu, v.w, 1);
    r = __shfl_down_sync(0xffffffffu, v.x, 1);
    if (lane16 == 0)  l = 0.f;
    if (lane16 == 15) r = 0.f;
}

__device__ __forceinline__ float4 conv_row(const float4& vm, float lm, float rm,
                                           const float4& vc, float lc, float rc_,
                                           const float4& vn, float ln, float rn,
                                           float w00, float w01, float w02,
                                           float w10, float w11, float w12,
                                           float w20, float w21, float w22)
{
    float4 o;
    o.x = w00*lm   + w01*vm.x + w02*vm.y
        + w10*lc   + w11*vc.x + w12*vc.y
        + w20*ln   + w21*vn.x + w22*vn.y;
    o.y = w00*vm.x + w01*vm.y + w02*vm.z
        + w10*vc.x + w11*vc.y + w12*vc.z
        + w20*vn.x + w21*vn.y + w22*vn.z;
    o.z = w00*vm.y + w01*vm.z + w02*vm.w
        + w10*vc.y + w11*vc.z + w12*vc.w
        + w20*vn.y + w21*vn.z + w22*vn.w;
    o.w = w00*vm.z + w01*vm.w + w02*rm
        + w10*vc.z + w11*vc.w + w12*rc_
        + w20*vn.z + w21*vn.w + w22*rn;
    return o;
}

// Each 16-lane group owns ONE image; each thread runs BOTH 32-row strips
// (stream 0: rows 0-31, stream 1: rows 32-63) as independent register windows.
__global__ __launch_bounds__(256)
void dwconv3x3_dual_kernel(const float* __restrict__ x,
                           const float* __restrict__ Wf,
                           float* __restrict__ y)
{
    const int tid    = threadIdx.x;
    const int warp   = tid >> 5;
    const int lane   = tid & 31;
    const int lane16 = lane & 15;
    const int half   = lane >> 4;                        // image select within warp

    const int image = (blockIdx.x * 8 + warp) * 2 + half;   // 0..8191
    const int c     = image & (C_CH - 1);
    const int col   = lane16 << 2;                           // 0,4,...,60

    // Diagonal filter W[c][c][ky][kx].
    const float* wp = Wf + (size_t)c * (C_CH + 1) * 9;
    const float w00 = __ldg(wp + 0), w01 = __ldg(wp + 1), w02 = __ldg(wp + 2);
    const float w10 = __ldg(wp + 3), w11 = __ldg(wp + 4), w12 = __ldg(wp + 5);
    const float w20 = __ldg(wp + 6), w21 = __ldg(wp + 7), w22 = __ldg(wp + 8);

    const float* xin  = x + (size_t)image * (H_SP * W_SP) + col;
    float*       yout = y + (size_t)image * (H_SP * W_SP) + col;

    // Stream 0 window (rows r-1, r, r+1 around r=0) and stream 1 (around r=32).
    float4 vm0, vc0, vn0, vm1, vc1, vn1;
    float  lm0, rm0, lc0, rc0, ln0, rn0;
    float  lm1, rm1, lc1, rc1, ln1, rn1;

    vm0 = f4zero();                                          // row -1
    vc0 = __ldg((const float4*)(xin + 0 * W_SP));
    vn0 = __ldg((const float4*)(xin + 1 * W_SP));
    vm1 = __ldg((const float4*)(xin + 31 * W_SP));
    vc1 = __ldg((const float4*)(xin + 32 * W_SP));
    vn1 = __ldg((const float4*)(xin + 33 * W_SP));
    lm0 = rm0 = 0.f;
    halo(vc0, lane16, lc0, rc0);
    halo(vn0, lane16, ln0, rn0);
    halo(vm1, lane16, lm1, rm1);
    halo(vc1, lane16, lc1, rc1);
    halo(vn1, lane16, ln1, rn1);

    #pragma unroll 8
    for (int r = 0; r < 32; r++) {
        // Two independent prefetches, issued back-to-back.
        // Stream 0 reads rows 2..33: always in-bounds, no predicate.
        float4 vp0 = __ldg((const float4*)(xin + (r + 2) * W_SP));
        const int g1 = r + 34;                               // stream 1: rows 34..65
        float4 vp1 = (g1 < H_SP) ? __ldg((const float4*)(xin + g1 * W_SP)) : f4zero();

        // Compute both output rows from resident windows.
        float4 o0 = conv_row(vm0, lm0, rm0, vc0, lc0, rc0, vn0, ln0, rn0,
                             w00, w01, w02, w10, w11, w12, w20, w21, w22);
        *(float4*)(yout + r * W_SP) = o0;

        float4 o1 = conv_row(vm1, lm1, rm1, vc1, lc1, rc1, vn1, ln1, rn1,
                             w00, w01, w02, w10, w11, w12, w20, w21, w22);
        *(float4*)(yout + (r + 32) * W_SP) = o1;

        // Halo the prefetched rows, then slide both windows.
        float lp0, rp0, lp1, rp1;
        halo(vp0, lane16, lp0, rp0);
        halo(vp1, lane16, lp1, rp1);

        vm0 = vc0; lm0 = lc0; rm0 = rc0;
        vc0 = vn0; lc0 = ln0; rc0 = rn0;
        vn0 = vp0; ln0 = lp0; rn0 = rp0;

        vm1 = vc1; lm1 = lc1; rm1 = rc1;
        vc1 = vn1; lc1 = ln1; rc1 = rn1;
        vn1 = vp1; ln1 = lp1; rn1 = rp1;
    }
}

extern "C" void kernel_launch(void* const* d_in, const int* in_sizes, int n_in,
                              void* d_out, int out_size)
{
    const float* x  = (const float*)d_in[0];   // (S,B,C,H,W) fp32
    const float* Wf = (const float*)d_in[1];   // (C,C,3,3)  fp32
    float* y = (float*)d_out;

    // 2 images per warp, 8 warps per block -> 16 images per block.
    dwconv3x3_dual_kernel<<<N_IMG / 16, 256>>>(x, Wf, y);
}

// round 8
// speedup vs baseline: 1.0524x; 1.0524x over previous
#include <cuda_runtime.h>
#include <cuda_bf16.h>

// Depthwise 3x3 conv, pad=1: x (2,16,256,64,64) fp32, W (256,256,3,3) -> diag only.
#define C_CH   256
#define H_SP   64
#define W_SP   64
#define N_IMG  (2 * 16 * C_CH)   // 8192 images of 64x64
#define HALF_H 32

__device__ __forceinline__ float4 f4zero() { return make_float4(0.f, 0.f, 0.f, 0.f); }

// Horizontal halo for one row: l = previous lane's .w, r = next lane's .x,
// zeroed at the 16-lane group boundaries (each group is an independent strip).
__device__ __forceinline__ void halo(const float4& v, int lane16, float& l, float& r)
{
    l = __shfl_up_sync(0xffffffffu, v.w, 1);
    r = __shfl_down_sync(0xffffffffu, v.x, 1);
    if (lane16 == 0)  l = 0.f;
    if (lane16 == 15) r = 0.f;
}

__global__ __launch_bounds__(256, 6)   // cap regs at 42 -> 48 resident warps/SM
void dwconv3x3_reg_kernel(const float* __restrict__ x,
                          const float* __restrict__ Wf,
                          float* __restrict__ y)
{
    const int tid    = threadIdx.x;
    const int warp   = tid >> 5;
    const int lane   = tid & 31;
    const int lane16 = lane & 15;

    // One warp = one image. Lanes 0-15: rows [0,32). Lanes 16-31: rows [32,64).
    const int image = blockIdx.x * 8 + warp;            // 0..8191
    const int c     = image & (C_CH - 1);
    const int top   = (lane >> 4) * HALF_H;             // 0 or 32
    const int col   = lane16 << 2;                      // 0,4,...,60

    // Diagonal filter W[c][c][ky][kx] — warp-uniform.
    const float* wp = Wf + (size_t)c * (C_CH + 1) * 9;
    const float w00 = __ldg(wp + 0), w01 = __ldg(wp + 1), w02 = __ldg(wp + 2);
    const float w10 = __ldg(wp + 3), w11 = __ldg(wp + 4), w12 = __ldg(wp + 5);
    const float w20 = __ldg(wp + 6), w21 = __ldg(wp + 7), w22 = __ldg(wp + 8);

    const float* xin  = x + (size_t)image * (H_SP * W_SP) + col;
    float*       yout = y + (size_t)image * (H_SP * W_SP) + col;

    // Register sliding window: rows (m)inus, (c)enter, (n)ext + their halos.
    float4 vm, vc, vn;
    float  lm, rm, lc, rc_, ln, rn;

    // Preload rows top-1, top, top+1 (top+1 <= 33 always valid; top-1 < 0 -> zero).
    vm = (top - 1 >= 0) ? __ldg((const float4*)(xin + (top - 1) * W_SP)) : f4zero();
    vc = __ldg((const float4*)(xin + top * W_SP));
    vn = __ldg((const float4*)(xin + (top + 1) * W_SP));
    halo(vm, lane16, lm, rm);
    halo(vc, lane16, lc, rc_);
    halo(vn, lane16, ln, rn);

    #pragma unroll 8
    for (int r = 0; r < HALF_H; r++) {
        // Prefetch row top+r+2 (zero past the image bottom).
        const int gpre = top + r + 2;
        float4 vp = (gpre < H_SP) ? __ldg((const float4*)(xin + gpre * W_SP)) : f4zero();
        float lp, rp;
        halo(vp, lane16, lp, rp);

        // Compute output row top+r.
        float4 o;
        o.x = w00*lm   + w01*vm.x + w02*vm.y
            + w10*lc   + w11*vc.x + w12*vc.y
            + w20*ln   + w21*vn.x + w22*vn.y;
        o.y = w00*vm.x + w01*vm.y + w02*vm.z
            + w10*vc.x + w11*vc.y + w12*vc.z
            + w20*vn.x + w21*vn.y + w22*vn.z;
        o.z = w00*vm.y + w01*vm.z + w02*vm.w
            + w10*vc.y + w11*vc.z + w12*vc.w
            + w20*vn.y + w21*vn.z + w22*vn.w;
        o.w = w00*vm.z + w01*vm.w + w02*rm
            + w10*vc.z + w11*vc.w + w12*rc_
            + w20*vn.z + w21*vn.w + w22*rn;

        *(float4*)(yout + (top + r) * W_SP) = o;

        // Slide the window.
        vm = vc; lm = lc; rm = rc_;
        vc = vn; lc = ln; rc_ = rn;
        vn = vp; ln = lp; rn = rp;
    }
}

extern "C" void kernel_launch(void* const* d_in, const int* in_sizes, int n_in,
                              void* d_out, int out_size)
{
    const float* x  = (const float*)d_in[0];   // (S,B,C,H,W) fp32
    const float* Wf = (const float*)d_in[1];   // (C,C,3,3)  fp32
    float* y = (float*)d_out;

    dwconv3x3_reg_kernel<<<N_IMG / 8, 256>>>(x, Wf, y);
}

// round 9
// speedup vs baseline: 1.1557x; 1.0982x over previous
#include <cuda_runtime.h>
#include <cuda_bf16.h>

// Depthwise 3x3 conv, pad=1: x (2,16,256,64,64) fp32, W (256,256,3,3) -> diag only.
#define C_CH   256
#define H_SP   64
#define W_SP   64
#define N_IMG  (2 * 16 * C_CH)   // 8192 images of 64x64
#define HALF_H 32

__device__ __forceinline__ float4 f4zero() { return make_float4(0.f, 0.f, 0.f, 0.f); }

// Horizontal halo for one row: l = previous lane's .w, r = next lane's .x,
// zeroed at the 16-lane group boundaries (each group is an independent strip).
__device__ __forceinline__ void halo(const float4& v, int lane16, float& l, float& r)
{
    l = __shfl_up_sync(0xffffffffu, v.w, 1);
    r = __shfl_down_sync(0xffffffffu, v.x, 1);
    if (lane16 == 0)  l = 0.f;
    if (lane16 == 15) r = 0.f;
}

__global__ __launch_bounds__(256)
void dwconv3x3_fu_kernel(const float* __restrict__ x,
                         const float* __restrict__ Wf,
                         float* __restrict__ y)
{
    const int tid    = threadIdx.x;
    const int warp   = tid >> 5;
    const int lane   = tid & 31;
    const int lane16 = lane & 15;

    // One warp = one image. Lanes 0-15: rows [0,32). Lanes 16-31: rows [32,64).
    const int image = blockIdx.x * 8 + warp;            // 0..8191
    const int c     = image & (C_CH - 1);
    const int top   = (lane >> 4) * HALF_H;             // 0 or 32
    const int col   = lane16 << 2;                      // 0,4,...,60

    // Diagonal filter W[c][c][ky][kx] — warp-uniform.
    const float* wp = Wf + (size_t)c * (C_CH + 1) * 9;
    const float w00 = __ldg(wp + 0), w01 = __ldg(wp + 1), w02 = __ldg(wp + 2);
    const float w10 = __ldg(wp + 3), w11 = __ldg(wp + 4), w12 = __ldg(wp + 5);
    const float w20 = __ldg(wp + 6), w21 = __ldg(wp + 7), w22 = __ldg(wp + 8);

    const float* xin  = x + (size_t)image * (H_SP * W_SP) + col;
    float*       yout = y + (size_t)image * (H_SP * W_SP) + col;

    // Register sliding window: rows (m)inus, (c)enter, (n)ext + their halos.
    float4 vm, vc, vn;
    float  lm, rm, lc, rc_, ln, rn;

    vm = (top - 1 >= 0) ? __ldg((const float4*)(xin + (top - 1) * W_SP)) : f4zero();
    vc = __ldg((const float4*)(xin + top * W_SP));
    vn = __ldg((const float4*)(xin + (top + 1) * W_SP));
    halo(vm, lane16, lm, rm);
    halo(vc, lane16, lc, rc_);
    halo(vn, lane16, ln, rn);

    // Fully unrolled: all 32 prefetch LDGs visible and UNCONDITIONAL
    // (clamped address, zero-select after) so ptxas can front-batch freely.
    #pragma unroll
    for (int r = 0; r < HALF_H; r++) {
        const int  gpre  = top + r + 2;
        const int  gclmp = (gpre < H_SP - 1) ? gpre : (H_SP - 1);   // always in-bounds
        const bool oob   = (gpre >= H_SP);

        float4 vp = __ldg((const float4*)(xin + gclmp * W_SP));     // unconditional issue
        if (oob) vp = f4zero();                                     // post-load select

        float lp, rp;
        halo(vp, lane16, lp, rp);

        // Compute output row top+r from resident window.
        float4 o;
        o.x = w00*lm   + w01*vm.x + w02*vm.y
            + w10*lc   + w11*vc.x + w12*vc.y
            + w20*ln   + w21*vn.x + w22*vn.y;
        o.y = w00*vm.x + w01*vm.y + w02*vm.z
            + w10*vc.x + w11*vc.y + w12*vc.z
            + w20*vn.x + w21*vn.y + w22*vn.z;
        o.z = w00*vm.y + w01*vm.z + w02*vm.w
            + w10*vc.y + w11*vc.z + w12*vc.w
            + w20*vn.y + w21*vn.z + w22*vn.w;
        o.w = w00*vm.z + w01*vm.w + w02*rm
            + w10*vc.z + w11*vc.w + w12*rc_
            + w20*vn.z + w21*vn.w + w22*rn;

        *(float4*)(yout + (top + r) * W_SP) = o;

        // Slide the window.
        vm = vc; lm = lc; rm = rc_;
        vc = vn; lc = ln; rc_ = rn;
        vn = vp; ln = lp; rn = rp;
    }
}

extern "C" void kernel_launch(void* const* d_in, const int* in_sizes, int n_in,
                              void* d_out, int out_size)
{
    const float* x  = (const float*)d_in[0];   // (S,B,C,H,W) fp32
    const float* Wf = (const float*)d_in[1];   // (C,C,3,3)  fp32
    float* y = (float*)d_out;

    dwconv3x3_fu_kernel<<<N_IMG / 8, 256>>>(x, Wf, y);
}